// round 1
// baseline (speedup 1.0000x reference)
#include <cuda_runtime.h>
#include <math.h>

#define N_TOK 8192
#define DM    1024
#define DFF   4096
#define NE    8
#define PD    256

// ---------------- scratch (device globals: no allocs allowed) ----------------
__device__ float g_h[(size_t)16384 * 4096];   // relu(fc1) per pair  (256 MB)
__device__ float g_y[(size_t)16384 * 1024];   // fc2 output per pair (64 MB)
__device__ float g_proj[(size_t)N_TOK * PD];  // projection          (8 MB)
__device__ float g_simn[PD * NE];             // column-normalized sim matrix
__device__ int   g_cnt[NE];
__device__ int   g_cursor[NE];
__device__ int   g_offset[NE + 1];
__device__ int   g_pair_tok[2 * N_TOK];       // global pair slot -> token
__device__ int   g_tok_e[2 * N_TOK];          // token -> its 2 experts
__device__ float g_tok_g[2 * N_TOK];          // token -> its 2 gates
__device__ int   g_tok_slot[2 * N_TOK];       // token -> its 2 global slots

// ---------------- f32x2 packed-FMA helpers (2x fp32 FFMA throughput) --------
__device__ __forceinline__ unsigned long long pk2(float lo, float hi) {
    unsigned long long r;
    asm("mov.b64 %0, {%1,%2};" : "=l"(r) : "f"(lo), "f"(hi));
    return r;
}
__device__ __forceinline__ void ffma2(unsigned long long &c,
                                      unsigned long long a,
                                      unsigned long long b) {
    asm("fma.rn.f32x2 %0, %1, %2, %0;" : "+l"(c) : "l"(a), "l"(b));
}
__device__ __forceinline__ void upk2(unsigned long long c, float &lo, float &hi) {
    asm("mov.b64 {%0,%1}, %2;" : "=f"(lo), "=f"(hi) : "l"(c));
}

// ---------------- prep: zero counters + L2-normalize sim_matrix columns -----
__global__ void prep_kernel(const float* __restrict__ sim) {
    int tid = threadIdx.x;
    if (tid < NE) { g_cnt[tid] = 0; g_cursor[tid] = 0; }
    int e = tid >> 5, lane = tid & 31;   // 8 warps, one per expert column
    float v[8]; float ss = 0.f;
#pragma unroll
    for (int j = 0; j < 8; j++) {
        v[j] = sim[(lane + 32 * j) * NE + e];
        ss += v[j] * v[j];
    }
#pragma unroll
    for (int o = 16; o > 0; o >>= 1) ss += __shfl_xor_sync(0xffffffffu, ss, o);
    float inv = 1.f / fmaxf(sqrtf(ss), 1e-12f);
#pragma unroll
    for (int j = 0; j < 8; j++) g_simn[(lane + 32 * j) * NE + e] = v[j] * inv;
}

// ---------------- generic 128x128x16 NT GEMM, f32x2 accumulators ------------
// C[M,N] = A[M,K] @ B[N,K]^T + bias, optional row gather (token lists),
// optional relu, optional per-expert grouping (blockIdx.z = expert).
template <bool GROUPED, bool GATHER, bool RELU>
__global__ void __launch_bounds__(256, 2)
gemm_nt(const float* __restrict__ A, const float* __restrict__ B,
        const float* __restrict__ bias, float* __restrict__ C,
        int M, int N, int K, long strideB, int strideBias) {
    __shared__ float As[16][128];
    __shared__ float Bs[16][128];
    __shared__ int   tok_s[128];

    int e = blockIdx.z;
    int rowbase = 0, Me = M;
    if (GROUPED) { rowbase = g_offset[e]; Me = g_offset[e + 1] - rowbase; }
    int m0 = blockIdx.y * 128;
    if (m0 >= Me) return;
    int nb = blockIdx.x * 128;
    const float* Bp = B + (long)e * strideB + (long)nb * K;

    int tid = threadIdx.x;
    if (GATHER) {
        if (tid < 128) {
            int r = min(m0 + tid, Me - 1);
            tok_s[tid] = g_pair_tok[rowbase + r];
        }
        __syncthreads();
    }

    int lrow = tid >> 2;            // 0..63
    int kq   = (tid & 3) << 2;      // 0,4,8,12
    const float *ap0, *ap1, *bp0, *bp1;
    {
        int r0 = min(m0 + lrow,      Me - 1);
        int r1 = min(m0 + lrow + 64, Me - 1);
        long i0 = GATHER ? (long)tok_s[r0 - m0] : (long)(rowbase + r0);
        long i1 = GATHER ? (long)tok_s[r1 - m0] : (long)(rowbase + r1);
        ap0 = A + i0 * K + kq;
        ap1 = A + i1 * K + kq;
        bp0 = Bp + (long)lrow * K + kq;
        bp1 = Bp + (long)(lrow + 64) * K + kq;
    }
    float4 ra0 = *(const float4*)ap0;
    float4 ra1 = *(const float4*)ap1;
    float4 rb0 = *(const float4*)bp0;
    float4 rb1 = *(const float4*)bp1;

    int ty = tid >> 4, tx = tid & 15;
    unsigned long long acc[8][4];
#pragma unroll
    for (int i = 0; i < 8; i++)
#pragma unroll
        for (int j = 0; j < 4; j++) acc[i][j] = 0ULL;

    for (int kt = 0; kt < K; kt += 16) {
        As[kq + 0][lrow] = ra0.x; As[kq + 1][lrow] = ra0.y;
        As[kq + 2][lrow] = ra0.z; As[kq + 3][lrow] = ra0.w;
        As[kq + 0][lrow + 64] = ra1.x; As[kq + 1][lrow + 64] = ra1.y;
        As[kq + 2][lrow + 64] = ra1.z; As[kq + 3][lrow + 64] = ra1.w;
        Bs[kq + 0][lrow] = rb0.x; Bs[kq + 1][lrow] = rb0.y;
        Bs[kq + 2][lrow] = rb0.z; Bs[kq + 3][lrow] = rb0.w;
        Bs[kq + 0][lrow + 64] = rb1.x; Bs[kq + 1][lrow + 64] = rb1.y;
        Bs[kq + 2][lrow + 64] = rb1.z; Bs[kq + 3][lrow + 64] = rb1.w;
        __syncthreads();
        if (kt + 16 < K) {
            ra0 = *(const float4*)(ap0 + kt + 16);
            ra1 = *(const float4*)(ap1 + kt + 16);
            rb0 = *(const float4*)(bp0 + kt + 16);
            rb1 = *(const float4*)(bp1 + kt + 16);
        }
#pragma unroll
        for (int kk = 0; kk < 16; kk++) {
            float4 a0 = *(const float4*)&As[kk][ty * 8];
            float4 a1 = *(const float4*)&As[kk][ty * 8 + 4];
            float4 b0 = *(const float4*)&Bs[kk][tx * 8];
            float4 b1 = *(const float4*)&Bs[kk][tx * 8 + 4];
            unsigned long long bb0 = pk2(b0.x, b0.y), bb1 = pk2(b0.z, b0.w);
            unsigned long long bb2 = pk2(b1.x, b1.y), bb3 = pk2(b1.z, b1.w);
            float av[8] = {a0.x, a0.y, a0.z, a0.w, a1.x, a1.y, a1.z, a1.w};
#pragma unroll
            for (int i = 0; i < 8; i++) {
                unsigned long long aa = pk2(av[i], av[i]);
                ffma2(acc[i][0], aa, bb0);
                ffma2(acc[i][1], aa, bb1);
                ffma2(acc[i][2], aa, bb2);
                ffma2(acc[i][3], aa, bb3);
            }
        }
        __syncthreads();
    }

    // epilogue: bias (+relu) + store
    float bv[8];
    const float* bp = bias + (GROUPED ? e * strideBias : 0) + nb + tx * 8;
#pragma unroll
    for (int j = 0; j < 8; j++) bv[j] = bp[j];
#pragma unroll
    for (int i = 0; i < 8; i++) {
        int r = m0 + ty * 8 + i;
        if (r < Me) {
            float* cp = C + (long)(rowbase + r) * N + nb + tx * 8;
#pragma unroll
            for (int j = 0; j < 4; j++) {
                float c0, c1;
                upk2(acc[i][j], c0, c1);
                c0 += bv[2 * j];
                c1 += bv[2 * j + 1];
                if (RELU) { c0 = fmaxf(c0, 0.f); c1 = fmaxf(c1, 0.f); }
                float2 st; st.x = c0; st.y = c1;
                *(float2*)(cp + 2 * j) = st;
            }
        }
    }
}

// ---------------- gate: cosine sim, top-2, softmax (one warp per token) -----
__global__ void gate_kernel(const float* __restrict__ temp) {
    int warp = threadIdx.x >> 5, lane = threadIdx.x & 31;
    int t = blockIdx.x * 8 + warp;
    const float* pr = g_proj + (size_t)t * PD;
    float pv[8]; float ss = 0.f;
#pragma unroll
    for (int j = 0; j < 8; j++) {
        pv[j] = pr[lane + 32 * j];
        ss += pv[j] * pv[j];
    }
#pragma unroll
    for (int o = 16; o > 0; o >>= 1) ss += __shfl_xor_sync(0xffffffffu, ss, o);
    float inv = 1.f / fmaxf(sqrtf(ss), 1e-12f);
    float acc[8] = {0, 0, 0, 0, 0, 0, 0, 0};
#pragma unroll
    for (int j = 0; j < 8; j++) {
        const float4* sp = (const float4*)(g_simn + (lane + 32 * j) * NE);
        float4 s0 = sp[0], s1 = sp[1];
        float p = pv[j];
        acc[0] += p * s0.x; acc[1] += p * s0.y; acc[2] += p * s0.z; acc[3] += p * s0.w;
        acc[4] += p * s1.x; acc[5] += p * s1.y; acc[6] += p * s1.z; acc[7] += p * s1.w;
    }
#pragma unroll
    for (int k = 0; k < 8; k++)
#pragma unroll
        for (int o = 16; o > 0; o >>= 1)
            acc[k] += __shfl_xor_sync(0xffffffffu, acc[k], o);
    if (lane == 0) {
        float tt = expf(temp[0]);
        float lg[8];
#pragma unroll
        for (int k = 0; k < 8; k++) lg[k] = acc[k] * inv * tt;
        int i0 = 0; float v0 = lg[0];
#pragma unroll
        for (int k = 1; k < 8; k++) if (lg[k] > v0) { v0 = lg[k]; i0 = k; }
        int i1 = (i0 == 0) ? 1 : 0; float v1 = lg[i1];
#pragma unroll
        for (int k = 0; k < 8; k++)
            if (k != i0 && lg[k] > v1) { v1 = lg[k]; i1 = k; }
        float ex = expf(v1 - v0);             // <= 1, stable
        float d  = 1.f / (1.f + ex);
        g_tok_e[2 * t] = i0; g_tok_e[2 * t + 1] = i1;
        g_tok_g[2 * t] = d;  g_tok_g[2 * t + 1] = ex * d;
        atomicAdd(&g_cnt[i0], 1);
        atomicAdd(&g_cnt[i1], 1);
    }
}

__global__ void offsets_kernel() {
    g_offset[0] = 0;
    for (int e = 0; e < NE; e++) g_offset[e + 1] = g_offset[e] + g_cnt[e];
}

__global__ void scatter_kernel() {
    int t = blockIdx.x * blockDim.x + threadIdx.x;
    if (t >= N_TOK) return;
#pragma unroll
    for (int j = 0; j < 2; j++) {
        int e = g_tok_e[2 * t + j];
        int slot = atomicAdd(&g_cursor[e], 1);
        int idx = g_offset[e] + slot;
        g_pair_tok[idx] = t;
        g_tok_slot[2 * t + j] = idx;
    }
}

// ---------------- combine: out[t] = g0*y[slot0] + g1*y[slot1] ---------------
__global__ void combine_kernel(float* __restrict__ out) {
    int t = blockIdx.x;
    int s0 = g_tok_slot[2 * t], s1 = g_tok_slot[2 * t + 1];
    float g0 = g_tok_g[2 * t], g1 = g_tok_g[2 * t + 1];
    int d = threadIdx.x;  // 256 threads x float4 = 1024 floats
    float4 y0 = ((const float4*)(g_y + (size_t)s0 * DM))[d];
    float4 y1 = ((const float4*)(g_y + (size_t)s1 * DM))[d];
    float4 o;
    o.x = g0 * y0.x + g1 * y1.x;
    o.y = g0 * y0.y + g1 * y1.y;
    o.z = g0 * y0.z + g1 * y1.z;
    o.w = g0 * y0.w + g1 * y1.w;
    ((float4*)(out + (size_t)t * DM))[d] = o;
}

// ---------------- launch --------------------------------------------------
extern "C" void kernel_launch(void* const* d_in, const int* in_sizes, int n_in,
                              void* d_out, int out_size) {
    const float* x    = (const float*)d_in[0];
    const float* cpw  = (const float*)d_in[1];
    const float* cpb  = (const float*)d_in[2];
    const float* sim  = (const float*)d_in[3];
    const float* temp = (const float*)d_in[4];
    const float* w1   = (const float*)d_in[5];
    const float* b1   = (const float*)d_in[6];
    const float* w2   = (const float*)d_in[7];
    const float* b2   = (const float*)d_in[8];
    float* out = (float*)d_out;

    void *ph, *py, *pproj;
    cudaGetSymbolAddress(&ph, g_h);
    cudaGetSymbolAddress(&py, g_y);
    cudaGetSymbolAddress(&pproj, g_proj);

    // 1. prep (counters + normalized sim matrix)
    prep_kernel<<<1, 256>>>(sim);
    // 2. proj = x @ cos_proj_w^T + b   [8192 x 256], K=1024
    gemm_nt<false, false, false><<<dim3(2, 64, 1), 256>>>(
        x, cpw, cpb, (float*)pproj, N_TOK, PD, DM, 0L, 0);
    // 3. cosine top-2 gate
    gate_kernel<<<N_TOK / 8, 256>>>(temp);
    // 4. prefix offsets
    offsets_kernel<<<1, 1>>>();
    // 5. scatter tokens into per-expert contiguous lists
    scatter_kernel<<<32, 256>>>();
    // 6. grouped GEMM1: h = relu(x_gathered @ W1^T + b1)  [pairs x 4096], K=1024
    gemm_nt<true, true, true><<<dim3(DFF / 128, N_TOK / 128, NE), 256>>>(
        x, w1, b1, (float*)ph, N_TOK, DFF, DM, (long)DFF * DM, DFF);
    // 7. grouped GEMM2: y = h @ W2^T + b2  [pairs x 1024], K=4096
    gemm_nt<true, false, false><<<dim3(DM / 128, N_TOK / 128, NE), 256>>>(
        (const float*)ph, w2, b2, (float*)py, N_TOK, DM, DFF, (long)DM * DFF, DM);
    // 8. gate-weighted combine
    combine_kernel<<<N_TOK, 256>>>(out);
}

// round 3
// speedup vs baseline: 2.4698x; 2.4698x over previous
#include <cuda_runtime.h>
#include <cuda_bf16.h>
#include <math.h>
#include <stdint.h>

#define N_TOK 8192
#define DM    1024
#define DFF   4096
#define NE    8
#define PD    256

// ---------------- scratch (device globals: no allocs allowed) ----------------
__device__ __nv_bfloat16 g_xh[(size_t)N_TOK * DM];
__device__ __nv_bfloat16 g_xl[(size_t)N_TOK * DM];
__device__ __nv_bfloat16 g_w1h[(size_t)NE * DFF * DM];
__device__ __nv_bfloat16 g_w1l[(size_t)NE * DFF * DM];
__device__ __nv_bfloat16 g_w2h[(size_t)NE * DM * DFF];
__device__ __nv_bfloat16 g_w2l[(size_t)NE * DM * DFF];
__device__ __nv_bfloat16 g_hh[(size_t)2 * N_TOK * DFF];
__device__ __nv_bfloat16 g_hl[(size_t)2 * N_TOK * DFF];
__device__ float g_y[(size_t)2 * N_TOK * DM];
__device__ float g_proj[(size_t)N_TOK * PD];
__device__ float g_simn[PD * NE];
__device__ int   g_cnt[NE];
__device__ int   g_cursor[NE];
__device__ int   g_offset[NE + 1];
__device__ int   g_pair_tok[2 * N_TOK];
__device__ int   g_tok_e[2 * N_TOK];
__device__ float g_tok_g[2 * N_TOK];
__device__ int   g_tok_slot[2 * N_TOK];

// ---------------- PTX helpers -------------------------------------------------
__device__ __forceinline__ uint32_t smem_u32(const void* p) {
    uint32_t a;
    asm("{ .reg .u64 t; cvta.to.shared.u64 t, %1; cvt.u32.u64 %0, t; }" : "=r"(a) : "l"(p));
    return a;
}
__device__ __forceinline__ void cp16(uint32_t dst, const void* src) {
    asm volatile("cp.async.cg.shared.global [%0], [%1], 16;" :: "r"(dst), "l"(src) : "memory");
}
__device__ __forceinline__ void cp_commit() {
    asm volatile("cp.async.commit_group;" ::: "memory");
}
template <int N>
__device__ __forceinline__ void cp_wait() {
    asm volatile("cp.async.wait_group %0;" :: "n"(N) : "memory");
}
__device__ __forceinline__ void ldsm4(uint32_t& r0, uint32_t& r1, uint32_t& r2, uint32_t& r3,
                                      uint32_t addr) {
    asm volatile("ldmatrix.sync.aligned.m8n8.x4.shared.b16 {%0,%1,%2,%3}, [%4];"
                 : "=r"(r0), "=r"(r1), "=r"(r2), "=r"(r3) : "r"(addr));
}
__device__ __forceinline__ void mma16816(float* d, const uint32_t* a, const uint32_t* b) {
    asm volatile(
        "mma.sync.aligned.m16n8k16.row.col.f32.bf16.bf16.f32 "
        "{%0,%1,%2,%3}, {%4,%5,%6,%7}, {%8,%9}, {%0,%1,%2,%3};"
        : "+f"(d[0]), "+f"(d[1]), "+f"(d[2]), "+f"(d[3])
        : "r"(a[0]), "r"(a[1]), "r"(a[2]), "r"(a[3]), "r"(b[0]), "r"(b[1]));
}
__device__ __forceinline__ uint32_t swz(uint32_t off) { return off ^ ((off >> 3) & 0x70); }

// SMEM layout for hgemm: bias[256]f | rows[128]i | 2 stages of 96KB
#define SM_BIAS  0
#define SM_ROWS  1024
#define SM_TILES 2048
#define OFF_AH   0
#define OFF_AL   16384
#define OFF_BH   32768
#define OFF_BL   65536
#define STAGE_B  98304
#define SMEM_TOTAL (SM_TILES + 2 * STAGE_B)

// ---------------- split fp32 -> bf16 hi/lo ------------------------------------
__global__ void split_kernel(const float4* __restrict__ src,
                             __nv_bfloat16* __restrict__ hi,
                             __nv_bfloat16* __restrict__ lo, long n4) {
    long stride = (long)gridDim.x * blockDim.x;
    for (long i = blockIdx.x * (long)blockDim.x + threadIdx.x; i < n4; i += stride) {
        float4 v = src[i];
        float vv[4] = {v.x, v.y, v.z, v.w};
        __nv_bfloat16 h[4], l[4];
#pragma unroll
        for (int j = 0; j < 4; j++) {
            h[j] = __float2bfloat16(vv[j]);
            l[j] = __float2bfloat16(vv[j] - __bfloat162float(h[j]));
        }
        __nv_bfloat162 h0; h0.x = h[0]; h0.y = h[1];
        __nv_bfloat162 h1; h1.x = h[2]; h1.y = h[3];
        __nv_bfloat162 l0; l0.x = l[0]; l0.y = l[1];
        __nv_bfloat162 l1; l1.x = l[2]; l1.y = l[3];
        ((__nv_bfloat162*)hi)[i * 2] = h0;
        ((__nv_bfloat162*)hi)[i * 2 + 1] = h1;
        ((__nv_bfloat162*)lo)[i * 2] = l0;
        ((__nv_bfloat162*)lo)[i * 2 + 1] = l1;
    }
}

// ---------------- mma.sync grouped GEMM: C = 3xbf16(A) @ 3xbf16(B)^T + bias ---
// CTA tile 128x256, BK=64, 512 threads (16 warps: 2 m x 8 n), warp tile 64x32.
template <bool GATHER, bool SPLITOUT>
__global__ void __launch_bounds__(512, 1)
hgemm(const __nv_bfloat16* __restrict__ Ah, const __nv_bfloat16* __restrict__ Al,
      const __nv_bfloat16* __restrict__ Bh, const __nv_bfloat16* __restrict__ Bl,
      const float* __restrict__ bias,
      float* __restrict__ Cf, __nv_bfloat16* __restrict__ Ch, __nv_bfloat16* __restrict__ Cl,
      int N, int K, long strideB, int strideBias) {
    extern __shared__ char smem[];
    uint32_t sb = smem_u32(smem);
    int tid = threadIdx.x;

    int e = blockIdx.z;
    int rowbase = g_offset[e];
    int Me = g_offset[e + 1] - rowbase;
    int m0 = blockIdx.y * 128;
    if (m0 >= Me) return;
    int nb = blockIdx.x * 256;

    float* bias_s = (float*)(smem + SM_BIAS);
    int*   rows_s = (int*)(smem + SM_ROWS);
    if (tid < 256) bias_s[tid] = bias[e * strideBias + nb + tid];
    if (tid < 128) {
        int r = min(m0 + tid, Me - 1);
        rows_s[tid] = GATHER ? g_pair_tok[rowbase + r] : (rowbase + r);
    }
    __syncthreads();

    size_t bbase = (size_t)e * strideB;
    const int nC = K / 64;

    // ---- cp.async stage loader ----
    auto load_stage = [&](int c) {
        uint32_t tb = sb + SM_TILES + (c & 1) * STAGE_B;
        int k0 = c * 64;
        // A: 1024 16B-chunks each for hi and lo (row = c>>3, kchunk = c&7)
#pragma unroll
        for (int j = 0; j < 2; j++) {
            int cch = tid + j * 512;
            int row = cch >> 3, kc = cch & 7;
            size_t ga = (size_t)rows_s[row] * K + k0 + kc * 8;
            uint32_t so = swz(row * 128 + kc * 16);
            cp16(tb + OFF_AH + so, Ah + ga);
            cp16(tb + OFF_AL + so, Al + ga);
        }
        // B: 2048 chunks each for hi and lo
#pragma unroll
        for (int j = 0; j < 4; j++) {
            int cch = tid + j * 512;
            int row = cch >> 3, kc = cch & 7;
            size_t gb = bbase + (size_t)(nb + row) * K + k0 + kc * 8;
            uint32_t so = swz(row * 128 + kc * 16);
            cp16(tb + OFF_BH + so, Bh + gb);
            cp16(tb + OFF_BL + so, Bl + gb);
        }
        cp_commit();
    };

    load_stage(0);
    load_stage(1);

    int wid = tid >> 5, lane = tid & 31;
    int warp_m = wid & 1;        // 0..1
    int warp_n = wid >> 1;       // 0..7
    // ldmatrix lane addressing constants
    int lrowA = warp_m * 64 + (lane & 7) + ((lane >> 3) & 1) * 8;   // + mf*16
    int lrowB = warp_n * 32 + (lane & 7) + ((lane >> 3) & 1) * 8;   // + nfp*16
    int lchunk = lane >> 4;                                          // 0/1

    float acc[4][4][4];
#pragma unroll
    for (int i = 0; i < 4; i++)
#pragma unroll
        for (int j = 0; j < 4; j++)
#pragma unroll
            for (int q = 0; q < 4; q++) acc[i][j][q] = 0.f;

    for (int c = 0; c < nC; c++) {
        if (c == nC - 1) cp_wait<0>(); else cp_wait<1>();
        __syncthreads();
        uint32_t tb = sb + SM_TILES + (c & 1) * STAGE_B;
#pragma unroll
        for (int ks = 0; ks < 4; ks++) {
            int chb = ks * 2 + lchunk;
            uint32_t ah[4][4], al[4][4];
#pragma unroll
            for (int mf = 0; mf < 4; mf++) {
                uint32_t so = swz((lrowA + mf * 16) * 128 + chb * 16);
                ldsm4(ah[mf][0], ah[mf][1], ah[mf][2], ah[mf][3], tb + OFF_AH + so);
                ldsm4(al[mf][0], al[mf][1], al[mf][2], al[mf][3], tb + OFF_AL + so);
            }
            uint32_t bh[4][2];
#pragma unroll
            for (int nfp = 0; nfp < 2; nfp++) {
                uint32_t r0, r1, r2, r3;
                uint32_t so = swz((lrowB + nfp * 16) * 128 + chb * 16);
                ldsm4(r0, r1, r2, r3, tb + OFF_BH + so);
                bh[2 * nfp][0] = r0; bh[2 * nfp][1] = r2;
                bh[2 * nfp + 1][0] = r1; bh[2 * nfp + 1][1] = r3;
            }
#pragma unroll
            for (int mf = 0; mf < 4; mf++)
#pragma unroll
                for (int nf = 0; nf < 4; nf++) {
                    mma16816(acc[mf][nf], ah[mf], bh[nf]);
                    mma16816(acc[mf][nf], al[mf], bh[nf]);
                }
            uint32_t bl[4][2];
#pragma unroll
            for (int nfp = 0; nfp < 2; nfp++) {
                uint32_t r0, r1, r2, r3;
                uint32_t so = swz((lrowB + nfp * 16) * 128 + chb * 16);
                ldsm4(r0, r1, r2, r3, tb + OFF_BL + so);
                bl[2 * nfp][0] = r0; bl[2 * nfp][1] = r2;
                bl[2 * nfp + 1][0] = r1; bl[2 * nfp + 1][1] = r3;
            }
#pragma unroll
            for (int mf = 0; mf < 4; mf++)
#pragma unroll
                for (int nf = 0; nf < 4; nf++)
                    mma16816(acc[mf][nf], ah[mf], bl[nf]);
        }
        __syncthreads();   // all warps done with buffer before refill
        if (c + 2 < nC) load_stage(c + 2);
    }

    // ---- epilogue ----
#pragma unroll
    for (int mf = 0; mf < 4; mf++) {
        int r0 = m0 + warp_m * 64 + mf * 16 + (lane >> 2);
        int r1 = r0 + 8;
#pragma unroll
        for (int nf = 0; nf < 4; nf++) {
            int colL = warp_n * 32 + nf * 8 + (lane & 3) * 2;  // within [0,256)
            float b0 = bias_s[colL], b1 = bias_s[colL + 1];
#pragma unroll
            for (int half = 0; half < 2; half++) {
                int r = half ? r1 : r0;
                if (r < Me) {
                    float v0 = acc[mf][nf][2 * half] + b0;
                    float v1 = acc[mf][nf][2 * half + 1] + b1;
                    size_t base = (size_t)(rowbase + r) * (size_t)N + nb + colL;
                    if (SPLITOUT) {
                        v0 = fmaxf(v0, 0.f); v1 = fmaxf(v1, 0.f);
                        __nv_bfloat16 h0 = __float2bfloat16(v0);
                        __nv_bfloat16 h1 = __float2bfloat16(v1);
                        __nv_bfloat16 l0 = __float2bfloat16(v0 - __bfloat162float(h0));
                        __nv_bfloat16 l1 = __float2bfloat16(v1 - __bfloat162float(h1));
                        __nv_bfloat162 hp; hp.x = h0; hp.y = h1;
                        __nv_bfloat162 lp; lp.x = l0; lp.y = l1;
                        *(__nv_bfloat162*)(Ch + base) = hp;
                        *(__nv_bfloat162*)(Cl + base) = lp;
                    } else {
                        float2 st; st.x = v0; st.y = v1;
                        *(float2*)(Cf + base) = st;
                    }
                }
            }
        }
    }
}

// ---------------- f32x2 packed-FMA helpers (proj GEMM) ------------------------
__device__ __forceinline__ unsigned long long pk2(float lo, float hi) {
    unsigned long long r;
    asm("mov.b64 %0, {%1,%2};" : "=l"(r) : "f"(lo), "f"(hi));
    return r;
}
__device__ __forceinline__ void ffma2(unsigned long long &c, unsigned long long a,
                                      unsigned long long b) {
    asm("fma.rn.f32x2 %0, %1, %2, %0;" : "+l"(c) : "l"(a), "l"(b));
}
__device__ __forceinline__ void upk2(unsigned long long c, float &lo, float &hi) {
    asm("mov.b64 {%0,%1}, %2;" : "=f"(lo), "=f"(hi) : "l"(c));
}

// ---------------- prep ---------------------------------------------------------
__global__ void prep_kernel(const float* __restrict__ sim) {
    int tid = threadIdx.x;
    if (tid < NE) { g_cnt[tid] = 0; g_cursor[tid] = 0; }
    int e = tid >> 5, lane = tid & 31;
    float v[8]; float ss = 0.f;
#pragma unroll
    for (int j = 0; j < 8; j++) {
        v[j] = sim[(lane + 32 * j) * NE + e];
        ss += v[j] * v[j];
    }
#pragma unroll
    for (int o = 16; o > 0; o >>= 1) ss += __shfl_xor_sync(0xffffffffu, ss, o);
    float inv = 1.f / fmaxf(sqrtf(ss), 1e-12f);
#pragma unroll
    for (int j = 0; j < 8; j++) g_simn[(lane + 32 * j) * NE + e] = v[j] * inv;
}

// ---------------- fp32 128x128x16 GEMM (proj only) -----------------------------
__global__ void __launch_bounds__(256, 2)
gemm_f32(const float* __restrict__ A, const float* __restrict__ B,
         const float* __restrict__ bias, float* __restrict__ C,
         int M, int N, int K) {
    __shared__ float As[16][128];
    __shared__ float Bs[16][128];
    int m0 = blockIdx.y * 128;
    int nb = blockIdx.x * 128;
    const float* Bp = B + (long)nb * K;
    int tid = threadIdx.x;
    int lrow = tid >> 2;
    int kq = (tid & 3) << 2;
    const float* ap0 = A + (long)(m0 + lrow) * K + kq;
    const float* ap1 = A + (long)(m0 + lrow + 64) * K + kq;
    const float* bp0 = Bp + (long)lrow * K + kq;
    const float* bp1 = Bp + (long)(lrow + 64) * K + kq;
    float4 ra0 = *(const float4*)ap0;
    float4 ra1 = *(const float4*)ap1;
    float4 rb0 = *(const float4*)bp0;
    float4 rb1 = *(const float4*)bp1;
    int ty = tid >> 4, tx = tid & 15;
    unsigned long long acc[8][4];
#pragma unroll
    for (int i = 0; i < 8; i++)
#pragma unroll
        for (int j = 0; j < 4; j++) acc[i][j] = 0ULL;
    for (int kt = 0; kt < K; kt += 16) {
        As[kq + 0][lrow] = ra0.x; As[kq + 1][lrow] = ra0.y;
        As[kq + 2][lrow] = ra0.z; As[kq + 3][lrow] = ra0.w;
        As[kq + 0][lrow + 64] = ra1.x; As[kq + 1][lrow + 64] = ra1.y;
        As[kq + 2][lrow + 64] = ra1.z; As[kq + 3][lrow + 64] = ra1.w;
        Bs[kq + 0][lrow] = rb0.x; Bs[kq + 1][lrow] = rb0.y;
        Bs[kq + 2][lrow] = rb0.z; Bs[kq + 3][lrow] = rb0.w;
        Bs[kq + 0][lrow + 64] = rb1.x; Bs[kq + 1][lrow + 64] = rb1.y;
        Bs[kq + 2][lrow + 64] = rb1.z; Bs[kq + 3][lrow + 64] = rb1.w;
        __syncthreads();
        if (kt + 16 < K) {
            ra0 = *(const float4*)(ap0 + kt + 16);
            ra1 = *(const float4*)(ap1 + kt + 16);
            rb0 = *(const float4*)(bp0 + kt + 16);
            rb1 = *(const float4*)(bp1 + kt + 16);
        }
#pragma unroll
        for (int kk = 0; kk < 16; kk++) {
            float4 a0 = *(const float4*)&As[kk][ty * 8];
            float4 a1 = *(const float4*)&As[kk][ty * 8 + 4];
            float4 b0 = *(const float4*)&Bs[kk][tx * 8];
            float4 b1 = *(const float4*)&Bs[kk][tx * 8 + 4];
            unsigned long long bb0 = pk2(b0.x, b0.y), bb1 = pk2(b0.z, b0.w);
            unsigned long long bb2 = pk2(b1.x, b1.y), bb3 = pk2(b1.z, b1.w);
            float av[8] = {a0.x, a0.y, a0.z, a0.w, a1.x, a1.y, a1.z, a1.w};
#pragma unroll
            for (int i = 0; i < 8; i++) {
                unsigned long long aa = pk2(av[i], av[i]);
                ffma2(acc[i][0], aa, bb0);
                ffma2(acc[i][1], aa, bb1);
                ffma2(acc[i][2], aa, bb2);
                ffma2(acc[i][3], aa, bb3);
            }
        }
        __syncthreads();
    }
    float bv[8];
    const float* bp = bias + nb + tx * 8;
#pragma unroll
    for (int j = 0; j < 8; j++) bv[j] = bp[j];
#pragma unroll
    for (int i = 0; i < 8; i++) {
        int r = m0 + ty * 8 + i;
        float* cp = C + (long)r * N + nb + tx * 8;
#pragma unroll
        for (int j = 0; j < 4; j++) {
            float c0, c1;
            upk2(acc[i][j], c0, c1);
            float2 st; st.x = c0 + bv[2 * j]; st.y = c1 + bv[2 * j + 1];
            *(float2*)(cp + 2 * j) = st;
        }
    }
}

// ---------------- gate: cosine sim, top-2, softmax ------------------------------
__global__ void gate_kernel(const float* __restrict__ temp) {
    int warp = threadIdx.x >> 5, lane = threadIdx.x & 31;
    int t = blockIdx.x * 8 + warp;
    const float* pr = g_proj + (size_t)t * PD;
    float pv[8]; float ss = 0.f;
#pragma unroll
    for (int j = 0; j < 8; j++) {
        pv[j] = pr[lane + 32 * j];
        ss += pv[j] * pv[j];
    }
#pragma unroll
    for (int o = 16; o > 0; o >>= 1) ss += __shfl_xor_sync(0xffffffffu, ss, o);
    float inv = 1.f / fmaxf(sqrtf(ss), 1e-12f);
    float acc[8] = {0, 0, 0, 0, 0, 0, 0, 0};
#pragma unroll
    for (int j = 0; j < 8; j++) {
        const float4* sp = (const float4*)(g_simn + (lane + 32 * j) * NE);
        float4 s0 = sp[0], s1 = sp[1];
        float p = pv[j];
        acc[0] += p * s0.x; acc[1] += p * s0.y; acc[2] += p * s0.z; acc[3] += p * s0.w;
        acc[4] += p * s1.x; acc[5] += p * s1.y; acc[6] += p * s1.z; acc[7] += p * s1.w;
    }
#pragma unroll
    for (int k = 0; k < 8; k++)
#pragma unroll
        for (int o = 16; o > 0; o >>= 1)
            acc[k] += __shfl_xor_sync(0xffffffffu, acc[k], o);
    if (lane == 0) {
        float tt = expf(temp[0]);
        float lg[8];
#pragma unroll
        for (int k = 0; k < 8; k++) lg[k] = acc[k] * inv * tt;
        int i0 = 0; float v0 = lg[0];
#pragma unroll
        for (int k = 1; k < 8; k++) if (lg[k] > v0) { v0 = lg[k]; i0 = k; }
        int i1 = (i0 == 0) ? 1 : 0; float v1 = lg[i1];
#pragma unroll
        for (int k = 0; k < 8; k++)
            if (k != i0 && lg[k] > v1) { v1 = lg[k]; i1 = k; }
        float ex = expf(v1 - v0);
        float d = 1.f / (1.f + ex);
        g_tok_e[2 * t] = i0; g_tok_e[2 * t + 1] = i1;
        g_tok_g[2 * t] = d;  g_tok_g[2 * t + 1] = ex * d;
        atomicAdd(&g_cnt[i0], 1);
        atomicAdd(&g_cnt[i1], 1);
    }
}

__global__ void offsets_kernel() {
    g_offset[0] = 0;
    for (int e = 0; e < NE; e++) g_offset[e + 1] = g_offset[e] + g_cnt[e];
}

__global__ void scatter_kernel() {
    int t = blockIdx.x * blockDim.x + threadIdx.x;
    if (t >= N_TOK) return;
#pragma unroll
    for (int j = 0; j < 2; j++) {
        int e = g_tok_e[2 * t + j];
        int slot = atomicAdd(&g_cursor[e], 1);
        int idx = g_offset[e] + slot;
        g_pair_tok[idx] = t;
        g_tok_slot[2 * t + j] = idx;
    }
}

__global__ void combine_kernel(float* __restrict__ out) {
    int t = blockIdx.x;
    int s0 = g_tok_slot[2 * t], s1 = g_tok_slot[2 * t + 1];
    float g0 = g_tok_g[2 * t], g1 = g_tok_g[2 * t + 1];
    int d = threadIdx.x;
    float4 y0 = ((const float4*)(g_y + (size_t)s0 * DM))[d];
    float4 y1 = ((const float4*)(g_y + (size_t)s1 * DM))[d];
    float4 o;
    o.x = g0 * y0.x + g1 * y1.x;
    o.y = g0 * y0.y + g1 * y1.y;
    o.z = g0 * y0.z + g1 * y1.z;
    o.w = g0 * y0.w + g1 * y1.w;
    ((float4*)(out + (size_t)t * DM))[d] = o;
}

// ---------------- launch --------------------------------------------------------
extern "C" void kernel_launch(void* const* d_in, const int* in_sizes, int n_in,
                              void* d_out, int out_size) {
    const float* x    = (const float*)d_in[0];
    const float* cpw  = (const float*)d_in[1];
    const float* cpb  = (const float*)d_in[2];
    const float* sim  = (const float*)d_in[3];
    const float* temp = (const float*)d_in[4];
    const float* w1   = (const float*)d_in[5];
    const float* b1   = (const float*)d_in[6];
    const float* w2   = (const float*)d_in[7];
    const float* b2   = (const float*)d_in[8];
    float* out = (float*)d_out;

    void *pxh, *pxl, *pw1h, *pw1l, *pw2h, *pw2l, *phh, *phl, *py, *pproj;
    cudaGetSymbolAddress(&pxh, g_xh);   cudaGetSymbolAddress(&pxl, g_xl);
    cudaGetSymbolAddress(&pw1h, g_w1h); cudaGetSymbolAddress(&pw1l, g_w1l);
    cudaGetSymbolAddress(&pw2h, g_w2h); cudaGetSymbolAddress(&pw2l, g_w2l);
    cudaGetSymbolAddress(&phh, g_hh);   cudaGetSymbolAddress(&phl, g_hl);
    cudaGetSymbolAddress(&py, g_y);     cudaGetSymbolAddress(&pproj, g_proj);

    cudaFuncSetAttribute(hgemm<true, true>,
                         cudaFuncAttributeMaxDynamicSharedMemorySize, SMEM_TOTAL);
    cudaFuncSetAttribute(hgemm<false, false>,
                         cudaFuncAttributeMaxDynamicSharedMemorySize, SMEM_TOTAL);

    prep_kernel<<<1, 256>>>(sim);
    split_kernel<<<592, 256>>>((const float4*)x, (__nv_bfloat16*)pxh,
                               (__nv_bfloat16*)pxl, (long)N_TOK * DM / 4);
    split_kernel<<<1184, 256>>>((const float4*)w1, (__nv_bfloat16*)pw1h,
                                (__nv_bfloat16*)pw1l, (long)NE * DFF * DM / 4);
    split_kernel<<<1184, 256>>>((const float4*)w2, (__nv_bfloat16*)pw2h,
                                (__nv_bfloat16*)pw2l, (long)NE * DM * DFF / 4);

    // proj = x @ cpw^T + cpb  (fp32 path; feeds top-k selection)
    gemm_f32<<<dim3(2, 64, 1), 256>>>(x, cpw, cpb, (float*)pproj, N_TOK, PD, DM);
    gate_kernel<<<N_TOK / 8, 256>>>(temp);
    offsets_kernel<<<1, 1>>>();
    scatter_kernel<<<32, 256>>>();

    // GEMM1: h = relu(x_gathered @ w1^T + b1), written as bf16 hi/lo
    hgemm<true, true><<<dim3(DFF / 256, 64, NE), 512, SMEM_TOTAL>>>(
        (const __nv_bfloat16*)pxh, (const __nv_bfloat16*)pxl,
        (const __nv_bfloat16*)pw1h, (const __nv_bfloat16*)pw1l,
        b1, nullptr, (__nv_bfloat16*)phh, (__nv_bfloat16*)phl,
        DFF, DM, (long)DFF * DM, DFF);

    // GEMM2: y = h @ w2^T + b2, fp32 out
    hgemm<false, false><<<dim3(DM / 256, 64, NE), 512, SMEM_TOTAL>>>(
        (const __nv_bfloat16*)phh, (const __nv_bfloat16*)phl,
        (const __nv_bfloat16*)pw2h, (const __nv_bfloat16*)pw2l,
        b2, (float*)py, nullptr, nullptr,
        DM, DFF, (long)DM * DFF, DM);

    combine_kernel<<<N_TOK, 256>>>(out);
}

// round 4
// speedup vs baseline: 2.5204x; 1.0205x over previous
#include <cuda_runtime.h>
#include <cuda_bf16.h>
#include <math.h>
#include <stdint.h>

#define N_TOK 8192
#define DM    1024
#define DFF   4096
#define NE    8
#define PD    256

// ---------------- scratch (device globals: no allocs allowed) ----------------
__device__ __nv_bfloat16 g_xh[(size_t)N_TOK * DM];
__device__ __nv_bfloat16 g_xl[(size_t)N_TOK * DM];
__device__ __nv_bfloat16 g_cpwh[(size_t)PD * DM];
__device__ __nv_bfloat16 g_cpwl[(size_t)PD * DM];
__device__ __nv_bfloat16 g_w1h[(size_t)NE * DFF * DM];
__device__ __nv_bfloat16 g_w1l[(size_t)NE * DFF * DM];
__device__ __nv_bfloat16 g_w2h[(size_t)NE * DM * DFF];
__device__ __nv_bfloat16 g_w2l[(size_t)NE * DM * DFF];
__device__ __nv_bfloat16 g_hh[(size_t)2 * N_TOK * DFF];
__device__ __nv_bfloat16 g_hl[(size_t)2 * N_TOK * DFF];
__device__ float g_y[(size_t)2 * N_TOK * DM];
__device__ float g_proj[(size_t)N_TOK * PD];
__device__ float g_simn[PD * NE];
__device__ int   g_cnt[NE];
__device__ int   g_cursor[NE];
__device__ int   g_offset[NE + 1];
__device__ int   g_pair_tok[2 * N_TOK];
__device__ int   g_tok_e[2 * N_TOK];
__device__ float g_tok_g[2 * N_TOK];
__device__ int   g_tok_slot[2 * N_TOK];

// ---------------- PTX helpers -------------------------------------------------
__device__ __forceinline__ uint32_t smem_u32(const void* p) {
    uint32_t a;
    asm("{ .reg .u64 t; cvta.to.shared.u64 t, %1; cvt.u32.u64 %0, t; }" : "=r"(a) : "l"(p));
    return a;
}
__device__ __forceinline__ void cp16(uint32_t dst, const void* src) {
    asm volatile("cp.async.cg.shared.global [%0], [%1], 16;" :: "r"(dst), "l"(src) : "memory");
}
__device__ __forceinline__ void cp_commit() {
    asm volatile("cp.async.commit_group;" ::: "memory");
}
template <int N>
__device__ __forceinline__ void cp_wait() {
    asm volatile("cp.async.wait_group %0;" :: "n"(N) : "memory");
}
__device__ __forceinline__ void ldsm4(uint32_t& r0, uint32_t& r1, uint32_t& r2, uint32_t& r3,
                                      uint32_t addr) {
    asm volatile("ldmatrix.sync.aligned.m8n8.x4.shared.b16 {%0,%1,%2,%3}, [%4];"
                 : "=r"(r0), "=r"(r1), "=r"(r2), "=r"(r3) : "r"(addr));
}
__device__ __forceinline__ void mma16816(float* d, const uint32_t* a, const uint32_t* b) {
    asm volatile(
        "mma.sync.aligned.m16n8k16.row.col.f32.bf16.bf16.f32 "
        "{%0,%1,%2,%3}, {%4,%5,%6,%7}, {%8,%9}, {%0,%1,%2,%3};"
        : "+f"(d[0]), "+f"(d[1]), "+f"(d[2]), "+f"(d[3])
        : "r"(a[0]), "r"(a[1]), "r"(a[2]), "r"(a[3]), "r"(b[0]), "r"(b[1]));
}
__device__ __forceinline__ uint32_t swz(uint32_t off) { return off ^ ((off >> 3) & 0x70); }

// SMEM layout for hgemm: bias[256]f | rows[128]i | 2 stages of 96KB
#define SM_BIAS  0
#define SM_ROWS  1024
#define SM_TILES 2048
#define OFF_AH   0
#define OFF_AL   16384
#define OFF_BH   32768
#define OFF_BL   65536
#define STAGE_B  98304
#define SMEM_TOTAL (SM_TILES + 2 * STAGE_B)

// ---------------- split fp32 -> bf16 hi/lo ------------------------------------
__global__ void split_kernel(const float4* __restrict__ src,
                             __nv_bfloat16* __restrict__ hi,
                             __nv_bfloat16* __restrict__ lo, long n4) {
    long stride = (long)gridDim.x * blockDim.x;
    for (long i = blockIdx.x * (long)blockDim.x + threadIdx.x; i < n4; i += stride) {
        float4 v = src[i];
        float vv[4] = {v.x, v.y, v.z, v.w};
        __nv_bfloat16 h[4], l[4];
#pragma unroll
        for (int j = 0; j < 4; j++) {
            h[j] = __float2bfloat16(vv[j]);
            l[j] = __float2bfloat16(vv[j] - __bfloat162float(h[j]));
        }
        __nv_bfloat162 h0; h0.x = h[0]; h0.y = h[1];
        __nv_bfloat162 h1; h1.x = h[2]; h1.y = h[3];
        __nv_bfloat162 l0; l0.x = l[0]; l0.y = l[1];
        __nv_bfloat162 l1; l1.x = l[2]; l1.y = l[3];
        ((__nv_bfloat162*)hi)[i * 2] = h0;
        ((__nv_bfloat162*)hi)[i * 2 + 1] = h1;
        ((__nv_bfloat162*)lo)[i * 2] = l0;
        ((__nv_bfloat162*)lo)[i * 2 + 1] = l1;
    }
}

// ---------------- mma.sync GEMM: C = 3xbf16(A) @ 3xbf16(B)^T + bias -----------
// CTA tile 128x256, BK=64, 512 threads (16 warps: 2 m x 8 n), warp tile 64x32.
// Three product passes (AhBh, AlBh, AhBl) kept separate so same-accumulator
// HMMAs are 16 instructions apart (RAW distance >> pipe latency).
template <bool GROUPED, bool GATHER, bool SPLITOUT>
__global__ void __launch_bounds__(512, 1)
hgemm(const __nv_bfloat16* __restrict__ Ah, const __nv_bfloat16* __restrict__ Al,
      const __nv_bfloat16* __restrict__ Bh, const __nv_bfloat16* __restrict__ Bl,
      const float* __restrict__ bias,
      float* __restrict__ Cf, __nv_bfloat16* __restrict__ Ch, __nv_bfloat16* __restrict__ Cl,
      int M, int N, int K, long strideB, int strideBias) {
    extern __shared__ char smem[];
    uint32_t sb = smem_u32(smem);
    int tid = threadIdx.x;

    int e = blockIdx.z;
    int rowbase = 0, Me = M;
    if (GROUPED) { rowbase = g_offset[e]; Me = g_offset[e + 1] - rowbase; }
    int m0 = blockIdx.y * 128;
    if (m0 >= Me) return;
    int nb = blockIdx.x * 256;
    int nblk = min(256, N - nb);   // N=256 path always full; kept for safety

    float* bias_s = (float*)(smem + SM_BIAS);
    int*   rows_s = (int*)(smem + SM_ROWS);
    if (tid < 256) bias_s[tid] = bias[(GROUPED ? e * strideBias : 0) + nb + min(tid, nblk - 1)];
    if (tid < 128) {
        int r = min(m0 + tid, Me - 1);
        rows_s[tid] = GATHER ? g_pair_tok[rowbase + r] : (rowbase + r);
    }
    __syncthreads();

    size_t bbase = GROUPED ? (size_t)e * strideB : 0;
    const int nC = K / 64;

    // ---- cp.async stage loader ----
    auto load_stage = [&](int c) {
        uint32_t tb = sb + SM_TILES + (c & 1) * STAGE_B;
        int k0 = c * 64;
#pragma unroll
        for (int j = 0; j < 2; j++) {
            int cch = tid + j * 512;
            int row = cch >> 3, kc = cch & 7;
            size_t ga = (size_t)rows_s[row] * K + k0 + kc * 8;
            uint32_t so = swz(row * 128 + kc * 16);
            cp16(tb + OFF_AH + so, Ah + ga);
            cp16(tb + OFF_AL + so, Al + ga);
        }
#pragma unroll
        for (int j = 0; j < 4; j++) {
            int cch = tid + j * 512;
            int row = cch >> 3, kc = cch & 7;
            int brow = min(row, nblk - 1);
            size_t gb = bbase + (size_t)(nb + brow) * K + k0 + kc * 8;
            uint32_t so = swz(row * 128 + kc * 16);
            cp16(tb + OFF_BH + so, Bh + gb);
            cp16(tb + OFF_BL + so, Bl + gb);
        }
        cp_commit();
    };

    load_stage(0);
    load_stage(1);

    int wid = tid >> 5, lane = tid & 31;
    int warp_m = wid & 1;        // 0..1
    int warp_n = wid >> 1;       // 0..7
    int lrowA = warp_m * 64 + (lane & 7) + ((lane >> 3) & 1) * 8;
    int lrowB = warp_n * 32 + (lane & 7) + ((lane >> 3) & 1) * 8;
    int lchunk = lane >> 4;

    float acc[4][4][4];
#pragma unroll
    for (int i = 0; i < 4; i++)
#pragma unroll
        for (int j = 0; j < 4; j++)
#pragma unroll
            for (int q = 0; q < 4; q++) acc[i][j][q] = 0.f;

    for (int c = 0; c < nC; c++) {
        if (c == nC - 1) cp_wait<0>(); else cp_wait<1>();
        __syncthreads();
        uint32_t tb = sb + SM_TILES + (c & 1) * STAGE_B;
#pragma unroll
        for (int ks = 0; ks < 4; ks++) {
            int chb = ks * 2 + lchunk;
            uint32_t ah[4][4], al[4][4];
#pragma unroll
            for (int mf = 0; mf < 4; mf++) {
                uint32_t so = swz((lrowA + mf * 16) * 128 + chb * 16);
                ldsm4(ah[mf][0], ah[mf][1], ah[mf][2], ah[mf][3], tb + OFF_AH + so);
                ldsm4(al[mf][0], al[mf][1], al[mf][2], al[mf][3], tb + OFF_AL + so);
            }
            uint32_t bh[4][2];
#pragma unroll
            for (int nfp = 0; nfp < 2; nfp++) {
                uint32_t r0, r1, r2, r3;
                uint32_t so = swz((lrowB + nfp * 16) * 128 + chb * 16);
                ldsm4(r0, r1, r2, r3, tb + OFF_BH + so);
                bh[2 * nfp][0] = r0; bh[2 * nfp][1] = r2;
                bh[2 * nfp + 1][0] = r1; bh[2 * nfp + 1][1] = r3;
            }
            uint32_t bl[4][2];
#pragma unroll
            for (int nfp = 0; nfp < 2; nfp++) {
                uint32_t r0, r1, r2, r3;
                uint32_t so = swz((lrowB + nfp * 16) * 128 + chb * 16);
                ldsm4(r0, r1, r2, r3, tb + OFF_BL + so);
                bl[2 * nfp][0] = r0; bl[2 * nfp][1] = r2;
                bl[2 * nfp + 1][0] = r1; bl[2 * nfp + 1][1] = r3;
            }
            // pass 1: Ah x Bh  (same-acc RAW distance = 16 mmas)
#pragma unroll
            for (int mf = 0; mf < 4; mf++)
#pragma unroll
                for (int nf = 0; nf < 4; nf++)
                    mma16816(acc[mf][nf], ah[mf], bh[nf]);
            // pass 2: Al x Bh
#pragma unroll
            for (int mf = 0; mf < 4; mf++)
#pragma unroll
                for (int nf = 0; nf < 4; nf++)
                    mma16816(acc[mf][nf], al[mf], bh[nf]);
            // pass 3: Ah x Bl
#pragma unroll
            for (int mf = 0; mf < 4; mf++)
#pragma unroll
                for (int nf = 0; nf < 4; nf++)
                    mma16816(acc[mf][nf], ah[mf], bl[nf]);
        }
        __syncthreads();
        if (c + 2 < nC) load_stage(c + 2);
    }

    // ---- epilogue ----
#pragma unroll
    for (int mf = 0; mf < 4; mf++) {
        int r0 = m0 + warp_m * 64 + mf * 16 + (lane >> 2);
        int r1 = r0 + 8;
#pragma unroll
        for (int nf = 0; nf < 4; nf++) {
            int colL = warp_n * 32 + nf * 8 + (lane & 3) * 2;
            float b0 = bias_s[colL], b1 = bias_s[colL + 1];
#pragma unroll
            for (int half = 0; half < 2; half++) {
                int r = half ? r1 : r0;
                if (r < Me) {
                    float v0 = acc[mf][nf][2 * half] + b0;
                    float v1 = acc[mf][nf][2 * half + 1] + b1;
                    size_t base = (size_t)(rowbase + r) * (size_t)N + nb + colL;
                    if (SPLITOUT) {
                        v0 = fmaxf(v0, 0.f); v1 = fmaxf(v1, 0.f);
                        __nv_bfloat16 h0 = __float2bfloat16(v0);
                        __nv_bfloat16 h1 = __float2bfloat16(v1);
                        __nv_bfloat16 l0 = __float2bfloat16(v0 - __bfloat162float(h0));
                        __nv_bfloat16 l1 = __float2bfloat16(v1 - __bfloat162float(h1));
                        __nv_bfloat162 hp; hp.x = h0; hp.y = h1;
                        __nv_bfloat162 lp; lp.x = l0; lp.y = l1;
                        *(__nv_bfloat162*)(Ch + base) = hp;
                        *(__nv_bfloat162*)(Cl + base) = lp;
                    } else {
                        float2 st; st.x = v0; st.y = v1;
                        *(float2*)(Cf + base) = st;
                    }
                }
            }
        }
    }
}

// ---------------- prep ---------------------------------------------------------
__global__ void prep_kernel(const float* __restrict__ sim) {
    int tid = threadIdx.x;
    if (tid < NE) { g_cnt[tid] = 0; g_cursor[tid] = 0; }
    int e = tid >> 5, lane = tid & 31;
    float v[8]; float ss = 0.f;
#pragma unroll
    for (int j = 0; j < 8; j++) {
        v[j] = sim[(lane + 32 * j) * NE + e];
        ss += v[j] * v[j];
    }
#pragma unroll
    for (int o = 16; o > 0; o >>= 1) ss += __shfl_xor_sync(0xffffffffu, ss, o);
    float inv = 1.f / fmaxf(sqrtf(ss), 1e-12f);
#pragma unroll
    for (int j = 0; j < 8; j++) g_simn[(lane + 32 * j) * NE + e] = v[j] * inv;
}

// ---------------- gate: cosine sim, top-2, softmax ------------------------------
__global__ void gate_kernel(const float* __restrict__ temp) {
    int warp = threadIdx.x >> 5, lane = threadIdx.x & 31;
    int t = blockIdx.x * 8 + warp;
    const float* pr = g_proj + (size_t)t * PD;
    float pv[8]; float ss = 0.f;
#pragma unroll
    for (int j = 0; j < 8; j++) {
        pv[j] = pr[lane + 32 * j];
        ss += pv[j] * pv[j];
    }
#pragma unroll
    for (int o = 16; o > 0; o >>= 1) ss += __shfl_xor_sync(0xffffffffu, ss, o);
    float inv = 1.f / fmaxf(sqrtf(ss), 1e-12f);
    float acc[8] = {0, 0, 0, 0, 0, 0, 0, 0};
#pragma unroll
    for (int j = 0; j < 8; j++) {
        const float4* sp = (const float4*)(g_simn + (lane + 32 * j) * NE);
        float4 s0 = sp[0], s1 = sp[1];
        float p = pv[j];
        acc[0] += p * s0.x; acc[1] += p * s0.y; acc[2] += p * s0.z; acc[3] += p * s0.w;
        acc[4] += p * s1.x; acc[5] += p * s1.y; acc[6] += p * s1.z; acc[7] += p * s1.w;
    }
#pragma unroll
    for (int k = 0; k < 8; k++)
#pragma unroll
        for (int o = 16; o > 0; o >>= 1)
            acc[k] += __shfl_xor_sync(0xffffffffu, acc[k], o);
    if (lane == 0) {
        float tt = expf(temp[0]);
        float lg[8];
#pragma unroll
        for (int k = 0; k < 8; k++) lg[k] = acc[k] * inv * tt;
        int i0 = 0; float v0 = lg[0];
#pragma unroll
        for (int k = 1; k < 8; k++) if (lg[k] > v0) { v0 = lg[k]; i0 = k; }
        int i1 = (i0 == 0) ? 1 : 0; float v1 = lg[i1];
#pragma unroll
        for (int k = 0; k < 8; k++)
            if (k != i0 && lg[k] > v1) { v1 = lg[k]; i1 = k; }
        float ex = expf(v1 - v0);
        float d = 1.f / (1.f + ex);
        g_tok_e[2 * t] = i0; g_tok_e[2 * t + 1] = i1;
        g_tok_g[2 * t] = d;  g_tok_g[2 * t + 1] = ex * d;
        atomicAdd(&g_cnt[i0], 1);
        atomicAdd(&g_cnt[i1], 1);
    }
}

__global__ void offsets_kernel() {
    g_offset[0] = 0;
    for (int e = 0; e < NE; e++) g_offset[e + 1] = g_offset[e] + g_cnt[e];
}

__global__ void scatter_kernel() {
    int t = blockIdx.x * blockDim.x + threadIdx.x;
    if (t >= N_TOK) return;
#pragma unroll
    for (int j = 0; j < 2; j++) {
        int e = g_tok_e[2 * t + j];
        int slot = atomicAdd(&g_cursor[e], 1);
        int idx = g_offset[e] + slot;
        g_pair_tok[idx] = t;
        g_tok_slot[2 * t + j] = idx;
    }
}

__global__ void combine_kernel(float* __restrict__ out) {
    int t = blockIdx.x;
    int s0 = g_tok_slot[2 * t], s1 = g_tok_slot[2 * t + 1];
    float g0 = g_tok_g[2 * t], g1 = g_tok_g[2 * t + 1];
    int d = threadIdx.x;
    float4 y0 = ((const float4*)(g_y + (size_t)s0 * DM))[d];
    float4 y1 = ((const float4*)(g_y + (size_t)s1 * DM))[d];
    float4 o;
    o.x = g0 * y0.x + g1 * y1.x;
    o.y = g0 * y0.y + g1 * y1.y;
    o.z = g0 * y0.z + g1 * y1.z;
    o.w = g0 * y0.w + g1 * y1.w;
    ((float4*)(out + (size_t)t * DM))[d] = o;
}

// ---------------- launch --------------------------------------------------------
extern "C" void kernel_launch(void* const* d_in, const int* in_sizes, int n_in,
                              void* d_out, int out_size) {
    const float* x    = (const float*)d_in[0];
    const float* cpw  = (const float*)d_in[1];
    const float* cpb  = (const float*)d_in[2];
    const float* sim  = (const float*)d_in[3];
    const float* temp = (const float*)d_in[4];
    const float* w1   = (const float*)d_in[5];
    const float* b1   = (const float*)d_in[6];
    const float* w2   = (const float*)d_in[7];
    const float* b2   = (const float*)d_in[8];
    float* out = (float*)d_out;

    void *pxh, *pxl, *pch, *pcl, *pw1h, *pw1l, *pw2h, *pw2l, *phh, *phl, *py, *pproj;
    cudaGetSymbolAddress(&pxh, g_xh);   cudaGetSymbolAddress(&pxl, g_xl);
    cudaGetSymbolAddress(&pch, g_cpwh); cudaGetSymbolAddress(&pcl, g_cpwl);
    cudaGetSymbolAddress(&pw1h, g_w1h); cudaGetSymbolAddress(&pw1l, g_w1l);
    cudaGetSymbolAddress(&pw2h, g_w2h); cudaGetSymbolAddress(&pw2l, g_w2l);
    cudaGetSymbolAddress(&phh, g_hh);   cudaGetSymbolAddress(&phl, g_hl);
    cudaGetSymbolAddress(&py, g_y);     cudaGetSymbolAddress(&pproj, g_proj);

    cudaFuncSetAttribute(hgemm<false, false, false>,
                         cudaFuncAttributeMaxDynamicSharedMemorySize, SMEM_TOTAL);
    cudaFuncSetAttribute(hgemm<true, true, true>,
                         cudaFuncAttributeMaxDynamicSharedMemorySize, SMEM_TOTAL);
    cudaFuncSetAttribute(hgemm<true, false, false>,
                         cudaFuncAttributeMaxDynamicSharedMemorySize, SMEM_TOTAL);

    prep_kernel<<<1, 256>>>(sim);
    split_kernel<<<592, 256>>>((const float4*)x, (__nv_bfloat16*)pxh,
                               (__nv_bfloat16*)pxl, (long)N_TOK * DM / 4);
    split_kernel<<<64, 256>>>((const float4*)cpw, (__nv_bfloat16*)pch,
                              (__nv_bfloat16*)pcl, (long)PD * DM / 4);
    split_kernel<<<1184, 256>>>((const float4*)w1, (__nv_bfloat16*)pw1h,
                                (__nv_bfloat16*)pw1l, (long)NE * DFF * DM / 4);
    split_kernel<<<1184, 256>>>((const float4*)w2, (__nv_bfloat16*)pw2h,
                                (__nv_bfloat16*)pw2l, (long)NE * DM * DFF / 4);

    // proj = x @ cpw^T + cpb on the tensor path (N=256 -> one x-block)
    hgemm<false, false, false><<<dim3(1, 64, 1), 512, SMEM_TOTAL>>>(
        (const __nv_bfloat16*)pxh, (const __nv_bfloat16*)pxl,
        (const __nv_bfloat16*)pch, (const __nv_bfloat16*)pcl,
        cpb, (float*)pproj, nullptr, nullptr,
        N_TOK, PD, DM, 0L, 0);

    gate_kernel<<<N_TOK / 8, 256>>>(temp);
    offsets_kernel<<<1, 1>>>();
    scatter_kernel<<<32, 256>>>();

    // GEMM1: h = relu(x_gathered @ w1^T + b1), written as bf16 hi/lo
    hgemm<true, true, true><<<dim3(DFF / 256, 64, NE), 512, SMEM_TOTAL>>>(
        (const __nv_bfloat16*)pxh, (const __nv_bfloat16*)pxl,
        (const __nv_bfloat16*)pw1h, (const __nv_bfloat16*)pw1l,
        b1, nullptr, (__nv_bfloat16*)phh, (__nv_bfloat16*)phl,
        2 * N_TOK, DFF, DM, (long)DFF * DM, DFF);

    // GEMM2: y = h @ w2^T + b2, fp32 out
    hgemm<true, false, false><<<dim3(DM / 256, 64, NE), 512, SMEM_TOTAL>>>(
        (const __nv_bfloat16*)phh, (const __nv_bfloat16*)phl,
        (const __nv_bfloat16*)pw2h, (const __nv_bfloat16*)pw2l,
        b2, (float*)py, nullptr, nullptr,
        2 * N_TOK, DM, DFF, (long)DM * DFF, DM);

    combine_kernel<<<N_TOK, 256>>>(out);
}

// round 5
// speedup vs baseline: 2.7964x; 1.1095x over previous
#include <cuda_runtime.h>
#include <cuda_bf16.h>
#include <math.h>
#include <stdint.h>

#define N_TOK 8192
#define DM    1024
#define DFF   4096
#define NE    8
#define PD    256

// ---------------- scratch (device globals: no allocs allowed) ----------------
__device__ __nv_bfloat16 g_xh[(size_t)N_TOK * DM];
__device__ __nv_bfloat16 g_xl[(size_t)N_TOK * DM];
__device__ __nv_bfloat16 g_cpwh[(size_t)PD * DM];
__device__ __nv_bfloat16 g_cpwl[(size_t)PD * DM];
__device__ __nv_bfloat16 g_w1h[(size_t)NE * DFF * DM];
__device__ __nv_bfloat16 g_w1l[(size_t)NE * DFF * DM];
__device__ __nv_bfloat16 g_w2h[(size_t)NE * DM * DFF];
__device__ __nv_bfloat16 g_w2l[(size_t)NE * DM * DFF];
__device__ __nv_bfloat16 g_hh[(size_t)2 * N_TOK * DFF];
__device__ __nv_bfloat16 g_hl[(size_t)2 * N_TOK * DFF];
__device__ float g_y[(size_t)2 * N_TOK * DM];
__device__ float g_proj[(size_t)N_TOK * PD];
__device__ float g_simn[PD * NE];
__device__ int   g_cnt[NE];
__device__ int   g_cursor[NE];
__device__ int   g_offset[NE + 1];
__device__ int   g_pair_tok[2 * N_TOK];
__device__ int   g_tok_e[2 * N_TOK];
__device__ float g_tok_g[2 * N_TOK];
__device__ int   g_tok_slot[2 * N_TOK];

// ---------------- PTX helpers -------------------------------------------------
__device__ __forceinline__ uint32_t smem_u32(const void* p) {
    uint32_t a;
    asm("{ .reg .u64 t; cvta.to.shared.u64 t, %1; cvt.u32.u64 %0, t; }" : "=r"(a) : "l"(p));
    return a;
}
__device__ __forceinline__ void cp16(uint32_t dst, const void* src) {
    asm volatile("cp.async.cg.shared.global [%0], [%1], 16;" :: "r"(dst), "l"(src) : "memory");
}
__device__ __forceinline__ void cp_commit() {
    asm volatile("cp.async.commit_group;" ::: "memory");
}
template <int N>
__device__ __forceinline__ void cp_wait() {
    asm volatile("cp.async.wait_group %0;" :: "n"(N) : "memory");
}
__device__ __forceinline__ void ldsm4(uint32_t& r0, uint32_t& r1, uint32_t& r2, uint32_t& r3,
                                      uint32_t addr) {
    asm volatile("ldmatrix.sync.aligned.m8n8.x4.shared.b16 {%0,%1,%2,%3}, [%4];"
                 : "=r"(r0), "=r"(r1), "=r"(r2), "=r"(r3) : "r"(addr));
}
__device__ __forceinline__ void mma16816(float* d, const uint32_t* a, const uint32_t* b) {
    asm volatile(
        "mma.sync.aligned.m16n8k16.row.col.f32.bf16.bf16.f32 "
        "{%0,%1,%2,%3}, {%4,%5,%6,%7}, {%8,%9}, {%0,%1,%2,%3};"
        : "+f"(d[0]), "+f"(d[1]), "+f"(d[2]), "+f"(d[3])
        : "r"(a[0]), "r"(a[1]), "r"(a[2]), "r"(a[3]), "r"(b[0]), "r"(b[1]));
}
// 64-byte-row swizzle: chunk bits [4:5] ^= row bits [7:8]  (conflict-free LDSM)
__device__ __forceinline__ uint32_t swz64(uint32_t off) { return off ^ ((off >> 3) & 0x30); }

// SMEM layout: bias[128]f | rows[128]i | 3 stages of 32KB
#define SM_BIAS  0
#define SM_ROWS  512
#define SM_TILES 1024
#define OFF_AH   0
#define OFF_AL   8192
#define OFF_BH   16384
#define OFF_BL   24576
#define STAGE_B  32768
#define SMEM_TOTAL (SM_TILES + 3 * STAGE_B)

// ---------------- split fp32 -> bf16 hi/lo ------------------------------------
__global__ void split_kernel(const float4* __restrict__ src,
                             __nv_bfloat16* __restrict__ hi,
                             __nv_bfloat16* __restrict__ lo, long n4) {
    long stride = (long)gridDim.x * blockDim.x;
    for (long i = blockIdx.x * (long)blockDim.x + threadIdx.x; i < n4; i += stride) {
        float4 v = src[i];
        float vv[4] = {v.x, v.y, v.z, v.w};
        __nv_bfloat16 h[4], l[4];
#pragma unroll
        for (int j = 0; j < 4; j++) {
            h[j] = __float2bfloat16(vv[j]);
            l[j] = __float2bfloat16(vv[j] - __bfloat162float(h[j]));
        }
        __nv_bfloat162 h0; h0.x = h[0]; h0.y = h[1];
        __nv_bfloat162 h1; h1.x = h[2]; h1.y = h[3];
        __nv_bfloat162 l0; l0.x = l[0]; l0.y = l[1];
        __nv_bfloat162 l1; l1.x = l[2]; l1.y = l[3];
        ((__nv_bfloat162*)hi)[i * 2] = h0;
        ((__nv_bfloat162*)hi)[i * 2 + 1] = h1;
        ((__nv_bfloat162*)lo)[i * 2] = l0;
        ((__nv_bfloat162*)lo)[i * 2 + 1] = l1;
    }
}

// ---------------- mma.sync GEMM: C = 3xbf16(A) @ 3xbf16(B)^T + bias -----------
// CTA tile 128x128, BK=32, 3-stage cp.async pipeline, 256 threads (8 warps:
// 2m x 4n, warp tile 64x32), 2 CTAs/SM. Grouped raster for L2 weight reuse.
template <bool GROUPED, bool GATHER, bool SPLITOUT>
__global__ void __launch_bounds__(256, 2)
hgemm(const __nv_bfloat16* __restrict__ Ah, const __nv_bfloat16* __restrict__ Al,
      const __nv_bfloat16* __restrict__ Bh, const __nv_bfloat16* __restrict__ Bl,
      const float* __restrict__ bias,
      float* __restrict__ Cf, __nv_bfloat16* __restrict__ Ch, __nv_bfloat16* __restrict__ Cl,
      int nx, int M, int N, int K, long strideB, int strideBias) {
    extern __shared__ char smem[];
    uint32_t sb = smem_u32(smem);
    int tid = threadIdx.x;

    // grouped raster: waves cover G n-blocks x many m-blocks (L2 reuse of B strips)
    int flat = blockIdx.x;
    int G = nx < 8 ? nx : 8;
    int gsz = G * 64;
    int grp = flat / gsz, rem = flat % gsz;
    int xi = grp * G + rem % G;
    int yi = rem / G;

    int e = blockIdx.z;
    int rowbase = 0, Me = M;
    if (GROUPED) { rowbase = g_offset[e]; Me = g_offset[e + 1] - rowbase; }
    int m0 = yi * 128;
    if (m0 >= Me) return;
    int nb = xi * 128;

    float* bias_s = (float*)(smem + SM_BIAS);
    int*   rows_s = (int*)(smem + SM_ROWS);
    if (tid < 128) {
        bias_s[tid] = bias[(GROUPED ? e * strideBias : 0) + nb + tid];
        int r = min(m0 + tid, Me - 1);
        rows_s[tid] = GATHER ? g_pair_tok[rowbase + r] : (rowbase + r);
    }
    __syncthreads();

    size_t bbase = GROUPED ? (size_t)e * strideB : 0;
    const int nC = K / 32;

    // ---- cp.async stage loader: 32KB/stage, 8 cp16 per thread ----
    auto load_stage = [&](int c) {
        uint32_t tb = sb + SM_TILES + (c % 3) * STAGE_B;
        int k0 = c * 32;
#pragma unroll
        for (int j = 0; j < 2; j++) {
            int idx = tid + j * 256;          // 0..511
            int row = idx >> 2, kc = idx & 3;
            uint32_t so = swz64(row * 64 + kc * 16);
            size_t ga = (size_t)rows_s[row] * K + k0 + kc * 8;
            cp16(tb + OFF_AH + so, Ah + ga);
            cp16(tb + OFF_AL + so, Al + ga);
            size_t gb = bbase + (size_t)(nb + row) * K + k0 + kc * 8;
            cp16(tb + OFF_BH + so, Bh + gb);
            cp16(tb + OFF_BL + so, Bl + gb);
        }
        cp_commit();
    };

    load_stage(0);
    load_stage(1);
    load_stage(2);

    int wid = tid >> 5, lane = tid & 31;
    int warp_m = wid & 1;        // 0..1
    int warp_n = wid >> 1;       // 0..3
    int lrowA = warp_m * 64 + (lane & 7) + ((lane >> 3) & 1) * 8;
    int lrowB = warp_n * 32 + (lane & 7) + ((lane >> 3) & 1) * 8;
    int lchunk = lane >> 4;

    float acc[4][4][4];
#pragma unroll
    for (int i = 0; i < 4; i++)
#pragma unroll
        for (int j = 0; j < 4; j++)
#pragma unroll
            for (int q = 0; q < 4; q++) acc[i][j][q] = 0.f;

    for (int c = 0; c < nC; c++) {
        if (c >= nC - 1) cp_wait<0>();
        else if (c == nC - 2) cp_wait<1>();
        else cp_wait<2>();
        __syncthreads();
        uint32_t tb = sb + SM_TILES + (c % 3) * STAGE_B;
#pragma unroll
        for (int ks = 0; ks < 2; ks++) {
            int chb = ks * 2 + lchunk;
            uint32_t ah[4][4], al[4][4];
#pragma unroll
            for (int mf = 0; mf < 4; mf++) {
                uint32_t so = swz64((lrowA + mf * 16) * 64 + chb * 16);
                ldsm4(ah[mf][0], ah[mf][1], ah[mf][2], ah[mf][3], tb + OFF_AH + so);
                ldsm4(al[mf][0], al[mf][1], al[mf][2], al[mf][3], tb + OFF_AL + so);
            }
            uint32_t bh[4][2], bl[4][2];
#pragma unroll
            for (int nfp = 0; nfp < 2; nfp++) {
                uint32_t r0, r1, r2, r3;
                uint32_t so = swz64((lrowB + nfp * 16) * 64 + chb * 16);
                ldsm4(r0, r1, r2, r3, tb + OFF_BH + so);
                bh[2 * nfp][0] = r0; bh[2 * nfp][1] = r2;
                bh[2 * nfp + 1][0] = r1; bh[2 * nfp + 1][1] = r3;
                ldsm4(r0, r1, r2, r3, tb + OFF_BL + so);
                bl[2 * nfp][0] = r0; bl[2 * nfp][1] = r2;
                bl[2 * nfp + 1][0] = r1; bl[2 * nfp + 1][1] = r3;
            }
            // three product passes, same-acc RAW distance = 16 mmas
#pragma unroll
            for (int mf = 0; mf < 4; mf++)
#pragma unroll
                for (int nf = 0; nf < 4; nf++)
                    mma16816(acc[mf][nf], ah[mf], bh[nf]);
#pragma unroll
            for (int mf = 0; mf < 4; mf++)
#pragma unroll
                for (int nf = 0; nf < 4; nf++)
                    mma16816(acc[mf][nf], al[mf], bh[nf]);
#pragma unroll
            for (int mf = 0; mf < 4; mf++)
#pragma unroll
                for (int nf = 0; nf < 4; nf++)
                    mma16816(acc[mf][nf], ah[mf], bl[nf]);
        }
        __syncthreads();
        if (c + 3 < nC) load_stage(c + 3);
    }

    // ---- epilogue ----
#pragma unroll
    for (int mf = 0; mf < 4; mf++) {
        int r0 = m0 + warp_m * 64 + mf * 16 + (lane >> 2);
        int r1 = r0 + 8;
#pragma unroll
        for (int nf = 0; nf < 4; nf++) {
            int colL = warp_n * 32 + nf * 8 + (lane & 3) * 2;
            float b0 = bias_s[colL], b1 = bias_s[colL + 1];
#pragma unroll
            for (int half = 0; half < 2; half++) {
                int r = half ? r1 : r0;
                if (r < Me) {
                    float v0 = acc[mf][nf][2 * half] + b0;
                    float v1 = acc[mf][nf][2 * half + 1] + b1;
                    size_t base = (size_t)(rowbase + r) * (size_t)N + nb + colL;
                    if (SPLITOUT) {
                        v0 = fmaxf(v0, 0.f); v1 = fmaxf(v1, 0.f);
                        __nv_bfloat16 h0 = __float2bfloat16(v0);
                        __nv_bfloat16 h1 = __float2bfloat16(v1);
                        __nv_bfloat16 l0 = __float2bfloat16(v0 - __bfloat162float(h0));
                        __nv_bfloat16 l1 = __float2bfloat16(v1 - __bfloat162float(h1));
                        __nv_bfloat162 hp; hp.x = h0; hp.y = h1;
                        __nv_bfloat162 lp; lp.x = l0; lp.y = l1;
                        *(__nv_bfloat162*)(Ch + base) = hp;
                        *(__nv_bfloat162*)(Cl + base) = lp;
                    } else {
                        float2 st; st.x = v0; st.y = v1;
                        *(float2*)(Cf + base) = st;
                    }
                }
            }
        }
    }
}

// ---------------- prep ---------------------------------------------------------
__global__ void prep_kernel(const float* __restrict__ sim) {
    int tid = threadIdx.x;
    if (tid < NE) { g_cnt[tid] = 0; g_cursor[tid] = 0; }
    int e = tid >> 5, lane = tid & 31;
    float v[8]; float ss = 0.f;
#pragma unroll
    for (int j = 0; j < 8; j++) {
        v[j] = sim[(lane + 32 * j) * NE + e];
        ss += v[j] * v[j];
    }
#pragma unroll
    for (int o = 16; o > 0; o >>= 1) ss += __shfl_xor_sync(0xffffffffu, ss, o);
    float inv = 1.f / fmaxf(sqrtf(ss), 1e-12f);
#pragma unroll
    for (int j = 0; j < 8; j++) g_simn[(lane + 32 * j) * NE + e] = v[j] * inv;
}

// ---------------- gate: cosine sim, top-2, softmax ------------------------------
__global__ void gate_kernel(const float* __restrict__ temp) {
    int warp = threadIdx.x >> 5, lane = threadIdx.x & 31;
    int t = blockIdx.x * 8 + warp;
    const float* pr = g_proj + (size_t)t * PD;
    float pv[8]; float ss = 0.f;
#pragma unroll
    for (int j = 0; j < 8; j++) {
        pv[j] = pr[lane + 32 * j];
        ss += pv[j] * pv[j];
    }
#pragma unroll
    for (int o = 16; o > 0; o >>= 1) ss += __shfl_xor_sync(0xffffffffu, ss, o);
    float inv = 1.f / fmaxf(sqrtf(ss), 1e-12f);
    float acc[8] = {0, 0, 0, 0, 0, 0, 0, 0};
#pragma unroll
    for (int j = 0; j < 8; j++) {
        const float4* sp = (const float4*)(g_simn + (lane + 32 * j) * NE);
        float4 s0 = sp[0], s1 = sp[1];
        float p = pv[j];
        acc[0] += p * s0.x; acc[1] += p * s0.y; acc[2] += p * s0.z; acc[3] += p * s0.w;
        acc[4] += p * s1.x; acc[5] += p * s1.y; acc[6] += p * s1.z; acc[7] += p * s1.w;
    }
#pragma unroll
    for (int k = 0; k < 8; k++)
#pragma unroll
        for (int o = 16; o > 0; o >>= 1)
            acc[k] += __shfl_xor_sync(0xffffffffu, acc[k], o);
    if (lane == 0) {
        float tt = expf(temp[0]);
        float lg[8];
#pragma unroll
        for (int k = 0; k < 8; k++) lg[k] = acc[k] * inv * tt;
        int i0 = 0; float v0 = lg[0];
#pragma unroll
        for (int k = 1; k < 8; k++) if (lg[k] > v0) { v0 = lg[k]; i0 = k; }
        int i1 = (i0 == 0) ? 1 : 0; float v1 = lg[i1];
#pragma unroll
        for (int k = 0; k < 8; k++)
            if (k != i0 && lg[k] > v1) { v1 = lg[k]; i1 = k; }
        float ex = expf(v1 - v0);
        float d = 1.f / (1.f + ex);
        g_tok_e[2 * t] = i0; g_tok_e[2 * t + 1] = i1;
        g_tok_g[2 * t] = d;  g_tok_g[2 * t + 1] = ex * d;
        atomicAdd(&g_cnt[i0], 1);
        atomicAdd(&g_cnt[i1], 1);
    }
}

__global__ void offsets_kernel() {
    g_offset[0] = 0;
    for (int e = 0; e < NE; e++) g_offset[e + 1] = g_offset[e] + g_cnt[e];
}

__global__ void scatter_kernel() {
    int t = blockIdx.x * blockDim.x + threadIdx.x;
    if (t >= N_TOK) return;
#pragma unroll
    for (int j = 0; j < 2; j++) {
        int e = g_tok_e[2 * t + j];
        int slot = atomicAdd(&g_cursor[e], 1);
        int idx = g_offset[e] + slot;
        g_pair_tok[idx] = t;
        g_tok_slot[2 * t + j] = idx;
    }
}

__global__ void combine_kernel(float* __restrict__ out) {
    int t = blockIdx.x;
    int s0 = g_tok_slot[2 * t], s1 = g_tok_slot[2 * t + 1];
    float g0 = g_tok_g[2 * t], g1 = g_tok_g[2 * t + 1];
    int d = threadIdx.x;
    float4 y0 = ((const float4*)(g_y + (size_t)s0 * DM))[d];
    float4 y1 = ((const float4*)(g_y + (size_t)s1 * DM))[d];
    float4 o;
    o.x = g0 * y0.x + g1 * y1.x;
    o.y = g0 * y0.y + g1 * y1.y;
    o.z = g0 * y0.z + g1 * y1.z;
    o.w = g0 * y0.w + g1 * y1.w;
    ((float4*)(out + (size_t)t * DM))[d] = o;
}

// ---------------- launch --------------------------------------------------------
extern "C" void kernel_launch(void* const* d_in, const int* in_sizes, int n_in,
                              void* d_out, int out_size) {
    const float* x    = (const float*)d_in[0];
    const float* cpw  = (const float*)d_in[1];
    const float* cpb  = (const float*)d_in[2];
    const float* sim  = (const float*)d_in[3];
    const float* temp = (const float*)d_in[4];
    const float* w1   = (const float*)d_in[5];
    const float* b1   = (const float*)d_in[6];
    const float* w2   = (const float*)d_in[7];
    const float* b2   = (const float*)d_in[8];
    float* out = (float*)d_out;

    void *pxh, *pxl, *pch, *pcl, *pw1h, *pw1l, *pw2h, *pw2l, *phh, *phl, *py, *pproj;
    cudaGetSymbolAddress(&pxh, g_xh);   cudaGetSymbolAddress(&pxl, g_xl);
    cudaGetSymbolAddress(&pch, g_cpwh); cudaGetSymbolAddress(&pcl, g_cpwl);
    cudaGetSymbolAddress(&pw1h, g_w1h); cudaGetSymbolAddress(&pw1l, g_w1l);
    cudaGetSymbolAddress(&pw2h, g_w2h); cudaGetSymbolAddress(&pw2l, g_w2l);
    cudaGetSymbolAddress(&phh, g_hh);   cudaGetSymbolAddress(&phl, g_hl);
    cudaGetSymbolAddress(&py, g_y);     cudaGetSymbolAddress(&pproj, g_proj);

    cudaFuncSetAttribute(hgemm<false, false, false>,
                         cudaFuncAttributeMaxDynamicSharedMemorySize, SMEM_TOTAL);
    cudaFuncSetAttribute(hgemm<true, true, true>,
                         cudaFuncAttributeMaxDynamicSharedMemorySize, SMEM_TOTAL);
    cudaFuncSetAttribute(hgemm<true, false, false>,
                         cudaFuncAttributeMaxDynamicSharedMemorySize, SMEM_TOTAL);

    prep_kernel<<<1, 256>>>(sim);
    split_kernel<<<592, 256>>>((const float4*)x, (__nv_bfloat16*)pxh,
                               (__nv_bfloat16*)pxl, (long)N_TOK * DM / 4);
    split_kernel<<<64, 256>>>((const float4*)cpw, (__nv_bfloat16*)pch,
                              (__nv_bfloat16*)pcl, (long)PD * DM / 4);
    split_kernel<<<1184, 256>>>((const float4*)w1, (__nv_bfloat16*)pw1h,
                                (__nv_bfloat16*)pw1l, (long)NE * DFF * DM / 4);
    split_kernel<<<1184, 256>>>((const float4*)w2, (__nv_bfloat16*)pw2h,
                                (__nv_bfloat16*)pw2l, (long)NE * DM * DFF / 4);

    // proj = x @ cpw^T + cpb on the tensor path (nx=2)
    hgemm<false, false, false><<<dim3(2 * 64, 1, 1), 256, SMEM_TOTAL>>>(
        (const __nv_bfloat16*)pxh, (const __nv_bfloat16*)pxl,
        (const __nv_bfloat16*)pch, (const __nv_bfloat16*)pcl,
        cpb, (float*)pproj, nullptr, nullptr,
        2, N_TOK, PD, DM, 0L, 0);

    gate_kernel<<<N_TOK / 8, 256>>>(temp);
    offsets_kernel<<<1, 1>>>();
    scatter_kernel<<<32, 256>>>();

    // GEMM1: h = relu(x_gathered @ w1^T + b1), written as bf16 hi/lo (nx=32)
    hgemm<true, true, true><<<dim3(32 * 64, 1, NE), 256, SMEM_TOTAL>>>(
        (const __nv_bfloat16*)pxh, (const __nv_bfloat16*)pxl,
        (const __nv_bfloat16*)pw1h, (const __nv_bfloat16*)pw1l,
        b1, nullptr, (__nv_bfloat16*)phh, (__nv_bfloat16*)phl,
        32, 2 * N_TOK, DFF, DM, (long)DFF * DM, DFF);

    // GEMM2: y = h @ w2^T + b2, fp32 out (nx=8)
    hgemm<true, false, false><<<dim3(8 * 64, 1, NE), 256, SMEM_TOTAL>>>(
        (const __nv_bfloat16*)phh, (const __nv_bfloat16*)phl,
        (const __nv_bfloat16*)pw2h, (const __nv_bfloat16*)pw2l,
        b2, (float*)py, nullptr, nullptr,
        8, 2 * N_TOK, DM, DFF, (long)DM * DFF, DM);

    combine_kernel<<<N_TOK, 256>>>(out);
}